// round 16
// baseline (speedup 1.0000x reference)
#include <cuda_runtime.h>
#include <cuda_bf16.h>
#include <math.h>

// Problem constants
#define T_STEPS 16384
#define D_IN    257
#define H_DIM   512
#define G4H     2048   // 4*H
#define O_DIM   257
#define REC_CTAS 64    // recurrence CTAs; each owns 8 hidden units
#define NREP    8      // replicas of the h-exchange buffer (spread L2 slices)

// Scratch (static __device__ arrays — no allocation allowed)
__device__ float    g_xg[(size_t)T_STEPS * G4H];   // 128 MB: precomputed input gates + biases
__device__ float    g_hs[(size_t)T_STEPS * H_DIM]; // 32 MB: h per timestep
// Tagged h exchange: [replica][parity][unit] -> (step_tag<<32)|float_bits
__device__ unsigned long long g_hx[NREP * 2 * H_DIM];

// ---------------------------------------------------------------------------
// init: reset exchange tags each launch (tags are monotonic within a launch)
// ---------------------------------------------------------------------------
__global__ void init_kernel() {
    const int idx = blockIdx.x * 256 + threadIdx.x;
    const int n = NREP * 2 * H_DIM;
    for (int i = idx; i < n; i += gridDim.x * 256) g_hx[i] = 0ull;
}

// ---------------------------------------------------------------------------
// Kernel A: x_gates[T, 4H] = stft @ W_ih^T + (b_ih + b_hh)
// ---------------------------------------------------------------------------
__global__ void __launch_bounds__(256) xgate_gemm(
    const float* __restrict__ stft, const float* __restrict__ W_ih,
    const float* __restrict__ b_ih, const float* __restrict__ b_hh)
{
    __shared__ float s_sh[16 * 260];  // row stride 260 (mult of 4 for float4)
    const int tid = threadIdx.x;
    const int t0  = blockIdx.x * 16;

    for (int r = 0; r < 16; r++)
        for (int d = tid; d < D_IN; d += 256)
            s_sh[r * 260 + d] = stft[(size_t)(t0 + r) * D_IN + d];
    __syncthreads();

    for (int cg = 0; cg < 8; cg++) {
        const int c = cg * 256 + tid;                  // 0..2047
        const float* wrow = W_ih + (size_t)c * D_IN;
        float acc[16];
        #pragma unroll
        for (int r = 0; r < 16; r++) acc[r] = 0.f;

        for (int dd = 0; dd < 64; dd++) {              // 64*4 = 256 of 257
            const float w0 = __ldg(wrow + dd * 4 + 0);
            const float w1 = __ldg(wrow + dd * 4 + 1);
            const float w2 = __ldg(wrow + dd * 4 + 2);
            const float w3 = __ldg(wrow + dd * 4 + 3);
            #pragma unroll
            for (int r = 0; r < 16; r++) {
                const float4 s4 = *reinterpret_cast<const float4*>(&s_sh[r * 260 + dd * 4]);
                float a = acc[r];
                a = fmaf(w0, s4.x, a);
                a = fmaf(w1, s4.y, a);
                a = fmaf(w2, s4.z, a);
                a = fmaf(w3, s4.w, a);
                acc[r] = a;
            }
        }
        const float wl = __ldg(wrow + 256);            // remainder d = 256
        #pragma unroll
        for (int r = 0; r < 16; r++) acc[r] = fmaf(wl, s_sh[r * 260 + 256], acc[r]);

        const float bias = __ldg(b_ih + c) + __ldg(b_hh + c);
        #pragma unroll
        for (int r = 0; r < 16; r++)
            g_xg[(size_t)(t0 + r) * G4H + c] = acc[r] + bias;
    }
}

// ---------------------------------------------------------------------------
// Kernel B: LSTM recurrence — SYMMETRIC warps, no warp-0 bottleneck, no red[].
// 64 persistent CTAs x 256 threads. CTA b owns units u0=8b..8b+7.
// Warp w owns unit u = u0+w END-TO-END:
//   lane l holds W_hh[g*512+u][k] for k = l+32j (j=0..15), all 4 gates (64 regs)
//   per step: full-512 dot from smem h (stride-32 scalar LDS, conflict-free)
//   -> 4-value warp butterfly (all lanes get i,f,g,o sums) -> redundant
//   pointwise in every lane -> lanes 0-7 publish unit to 8 replicas ->
//   poll own 64-word segment into parity buffer -> single __syncthreads.
// All 8 warps run identical code => minimal skew; gate reduction never
// leaves the warp.
// ---------------------------------------------------------------------------
__device__ __forceinline__ float fsigm(float x) { return 1.0f / (1.0f + __expf(-x)); }
__device__ __forceinline__ float ftanh(float x) { return 2.0f / (1.0f + __expf(-2.0f * x)) - 1.0f; }

__global__ void __launch_bounds__(256) lstm_rec(const float* __restrict__ W_hh)
{
    __shared__ float hseg[2][H_DIM];   // parity double-buffered h

    const int tid = threadIdx.x;
    const int b   = blockIdx.x;        // 0..63
    const int w   = tid >> 5;          // warp = unit index within CTA
    const int l   = tid & 31;
    const int u0  = b * 8;
    const int u   = u0 + w;            // this warp's hidden unit
    const int crep = b & (NREP - 1);   // replica this CTA polls

    // weights: wreg[g][j] = W_hh[g*512+u][l + 32j]
    float wreg[4][16];
    #pragma unroll
    for (int g = 0; g < 4; g++)
        #pragma unroll
        for (int j = 0; j < 16; j++)
            wreg[g][j] = __ldg(&W_hh[(size_t)(g * H_DIM + u) * H_DIM + l + 32 * j]);

    // zero both h buffers (h_0 = 0)
    for (int i = tid; i < 2 * H_DIM; i += 256) (&hseg[0][0])[i] = 0.f;

    float cst = 0.f;                   // c state (redundant per lane, identical)
    // xg double-buffer: xgA = even steps, xgB = odd steps (4 gates each)
    float xgA[4], xgB[4];
    #pragma unroll
    for (int g = 0; g < 4; g++) {
        xgA[g] = __ldg(&g_xg[(size_t)0 * G4H + g * H_DIM + u]);   // t=0
        xgB[g] = __ldg(&g_xg[(size_t)1 * G4H + g * H_DIM + u]);   // t=1
    }
    __syncthreads();

    for (int t = 0; t < T_STEPS; ++t) {
        float* xg = (t & 1) ? xgB : xgA;
        const float* hb = &hseg[t & 1][0];

        // full-512 dot: lane l covers k = l + 32j (conflict-free scalar LDS)
        float a0 = 0.f, a1 = 0.f, a2 = 0.f, a3 = 0.f;
        #pragma unroll
        for (int j = 0; j < 16; j++) {
            const float h = hb[l + 32 * j];
            a0 = fmaf(wreg[0][j], h, a0);
            a1 = fmaf(wreg[1][j], h, a1);
            a2 = fmaf(wreg[2][j], h, a2);
            a3 = fmaf(wreg[3][j], h, a3);
        }
        // butterfly: every lane gets the 4 full gate sums
        const unsigned FULL = 0xffffffffu;
        #pragma unroll
        for (int off = 16; off > 0; off >>= 1) {
            a0 += __shfl_xor_sync(FULL, a0, off);
            a1 += __shfl_xor_sync(FULL, a1, off);
            a2 += __shfl_xor_sync(FULL, a2, off);
            a3 += __shfl_xor_sync(FULL, a3, off);
        }

        const float ig = fsigm(a0 + xg[0]);
        const float ff = fsigm(a1 + xg[1]);
        const float gg = ftanh(a2 + xg[2]);
        const float oo = fsigm(a3 + xg[3]);
        cst = fmaf(ff, cst, ig * gg);
        const float hn = oo * ftanh(cst);

        // distance-2 xg prefetch (xg[] now dead; consumed 2 iterations later)
        if (t + 2 < T_STEPS) {
            #pragma unroll
            for (int g = 0; g < 4; g++)
                xg[g] = __ldg(&g_xg[(size_t)(t + 2) * G4H + g * H_DIM + u]);
        }

        const int par2 = (t + 1) & 1;
        // publish: lanes 0-7 -> one replica each (parallel stores)
        if (l < 8) {
            const unsigned long long word =
                ((unsigned long long)(unsigned)(t + 1) << 32) |
                (unsigned long long)__float_as_uint(hn);
            unsigned long long* dst = &g_hx[((size_t)(l * 2 + par2)) * H_DIM + u];
            asm volatile("st.global.relaxed.gpu.b64 [%0], %1;"
                         :: "l"(dst), "l"(word) : "memory");
        }
        if (l == 8) g_hs[(size_t)t * H_DIM + u] = hn;

        // poll own 64-word segment for step t+1 (2 b64 per lane)
        if (t + 1 < T_STEPS) {
            const unsigned tgt = (unsigned)(t + 1);
            unsigned long long* src =
                &g_hx[((size_t)(crep * 2 + par2)) * H_DIM + w * 64 + 2 * l];
            unsigned long long v0, v1;
            while (true) {
                asm volatile("ld.global.relaxed.gpu.b64 %0, [%1];"
                             : "=l"(v0) : "l"(src) : "memory");
                asm volatile("ld.global.relaxed.gpu.b64 %0, [%1];"
                             : "=l"(v1) : "l"(src + 1) : "memory");
                if ((unsigned)(v0 >> 32) == tgt && (unsigned)(v1 >> 32) == tgt) break;
            }
            hseg[par2][w * 64 + 2 * l]     = __uint_as_float((unsigned)v0);
            hseg[par2][w * 64 + 2 * l + 1] = __uint_as_float((unsigned)v1);
        }
        __syncthreads();   // single barrier per step
    }
}

// ---------------------------------------------------------------------------
// Kernel C: out = log_softmax(hs @ W_out^T + b_out)
// ---------------------------------------------------------------------------
__global__ void __launch_bounds__(256) out_kernel(
    const float* __restrict__ W_out, const float* __restrict__ b_out,
    float* __restrict__ out)
{
    __shared__ float hsm[8 * 512];
    __shared__ float red[256];
    const int tid = threadIdx.x;
    const int t0  = blockIdx.x * 8;

    for (int idx = tid; idx < 8 * 512; idx += 256)
        hsm[idx] = g_hs[(size_t)t0 * H_DIM + idx];
    __syncthreads();

    float acc[8], acc2[8];
    #pragma unroll
    for (int r = 0; r < 8; r++) { acc[r] = 0.f; acc2[r] = 0.f; }

    const float4* wr = reinterpret_cast<const float4*>(W_out + (size_t)tid * H_DIM);
    for (int kk = 0; kk < 128; kk++) {
        const float4 w4 = __ldg(wr + kk);
        #pragma unroll
        for (int rr = 0; rr < 8; rr++) {
            const float4 hv = *reinterpret_cast<const float4*>(&hsm[rr * 512 + kk * 4]);
            float a = acc[rr];
            a = fmaf(w4.x, hv.x, a);
            a = fmaf(w4.y, hv.y, a);
            a = fmaf(w4.z, hv.z, a);
            a = fmaf(w4.w, hv.w, a);
            acc[rr] = a;
        }
    }
    if (tid == 0) {  // column 256
        const float4* wr2 = reinterpret_cast<const float4*>(W_out + (size_t)256 * H_DIM);
        for (int kk = 0; kk < 128; kk++) {
            const float4 w4 = __ldg(wr2 + kk);
            #pragma unroll
            for (int rr = 0; rr < 8; rr++) {
                const float4 hv = *reinterpret_cast<const float4*>(&hsm[rr * 512 + kk * 4]);
                float a = acc2[rr];
                a = fmaf(w4.x, hv.x, a);
                a = fmaf(w4.y, hv.y, a);
                a = fmaf(w4.z, hv.z, a);
                a = fmaf(w4.w, hv.w, a);
                acc2[rr] = a;
            }
        }
    }

    const float bias  = __ldg(b_out + tid);
    const float bias2 = __ldg(b_out + 256);

    for (int r = 0; r < 8; r++) {
        const float z  = acc[r] + bias;
        const float z2 = acc2[r] + bias2;          // meaningful only for tid==0
        float m = (tid == 0) ? fmaxf(z, z2) : z;

        red[tid] = m; __syncthreads();
        for (int s = 128; s > 0; s >>= 1) {
            if (tid < s) red[tid] = fmaxf(red[tid], red[tid + s]);
            __syncthreads();
        }
        const float mx = red[0]; __syncthreads();

        float e = __expf(z - mx);
        if (tid == 0) e += __expf(z2 - mx);
        red[tid] = e; __syncthreads();
        for (int s = 128; s > 0; s >>= 1) {
            if (tid < s) red[tid] += red[tid + s];
            __syncthreads();
        }
        const float lse = logf(red[0]); __syncthreads();

        out[(size_t)(t0 + r) * O_DIM + tid] = z - mx - lse;
        if (tid == 0) out[(size_t)(t0 + r) * O_DIM + 256] = z2 - mx - lse;
    }
}

// ---------------------------------------------------------------------------
// kernel_launch: init -> input GEMM -> recurrence -> output GEMM+softmax
// ---------------------------------------------------------------------------
extern "C" void kernel_launch(void* const* d_in, const int* in_sizes, int n_in,
                              void* d_out, int out_size)
{
    const float* stft  = (const float*)d_in[0];
    const float* W_ih  = (const float*)d_in[1];
    const float* W_hh  = (const float*)d_in[2];
    const float* b_ih  = (const float*)d_in[3];
    const float* b_hh  = (const float*)d_in[4];
    const float* W_out = (const float*)d_in[5];
    const float* b_out = (const float*)d_in[6];
    float* out = (float*)d_out;

    init_kernel<<<8, 256>>>();
    xgate_gemm<<<T_STEPS / 16, 256>>>(stft, W_ih, b_ih, b_hh);
    lstm_rec<<<REC_CTAS, 256>>>(W_hh);
    out_kernel<<<T_STEPS / 8, 256>>>(W_out, b_out, out);
}